// round 3
// baseline (speedup 1.0000x reference)
#include <cuda_runtime.h>
#include <cuda_bf16.h>
#include <stdint.h>
#include <stddef.h>

#define DI __device__ __forceinline__

constexpr int BROWS = 16384;
constexpr int DIN   = 784;
constexpr int DH    = 4096;
constexpr int DOUT  = 10;
constexpr int KPAD  = 832;           // 784 padded to 13 chunks of 64
constexpr int NCHUNK = 13;

// ------------------------- scratch (device globals) -------------------------
__device__ __align__(1024) signed char g_xq[(size_t)BROWS * KPAD];   // 13.6 MB
__device__ __align__(1024) signed char g_w1q[(size_t)DH * KPAD];     // 3.4 MB
__device__ __align__(1024) float       g_h[(size_t)BROWS * DH];      // 268 MB
__device__ __align__(16)   signed char g_w2q[DOUT * DH];             // 40 KB
__device__ float g_ax[BROWS];
// [0]=s1 (w1 quant scale) [1]=s2 [2]=1/s1 (=wm1) [3]=1/s2 (=wm2)
__device__ float g_scalars[4];
__device__ float g_partial[512];

// ------------------------- small helpers -------------------------
DI float warp_sum(float v) {
#pragma unroll
    for (int o = 16; o > 0; o >>= 1) v += __shfl_xor_sync(0xffffffffu, v, o);
    return v;
}
DI float warp_max(float v) {
#pragma unroll
    for (int o = 16; o > 0; o >>= 1) v = fmaxf(v, __shfl_xor_sync(0xffffffffu, v, o));
    return v;
}
DI int warp_isum(int v) {
#pragma unroll
    for (int o = 16; o > 0; o >>= 1) v += __shfl_xor_sync(0xffffffffu, v, o);
    return v;
}
DI uint32_t smem_u32(const void* p) {
    uint32_t a;
    asm("{ .reg .u64 t; cvta.to.shared.u64 t, %1; cvt.u32.u64 %0, t; }" : "=r"(a) : "l"(p));
    return a;
}
DI void cp16(uint32_t dst, const void* src) {
    asm volatile("cp.async.cg.shared.global [%0], [%1], 16;" :: "r"(dst), "l"(src));
}
DI uint32_t lds32(uint32_t addr) {
    uint32_t v;
    asm volatile("ld.shared.b32 %0, [%1];" : "=r"(v) : "r"(addr));
    return v;
}
DI void mma_s8(int* c, uint32_t a0, uint32_t a1, uint32_t a2, uint32_t a3,
               uint32_t b0, uint32_t b1) {
    asm volatile(
        "mma.sync.aligned.m16n8k32.row.col.s32.s8.s8.s32 "
        "{%0,%1,%2,%3}, {%4,%5,%6,%7}, {%8,%9}, {%0,%1,%2,%3};"
        : "+r"(c[0]), "+r"(c[1]), "+r"(c[2]), "+r"(c[3])
        : "r"(a0), "r"(a1), "r"(a2), "r"(a3), "r"(b0), "r"(b1));
}

// ------------------------- weight-scale reductions -------------------------
__global__ void k_w1_partial(const float* __restrict__ w1) {
    __shared__ float s_red[8];
    int t = threadIdx.x;
    float s = 0.f;
    const size_t total = (size_t)DH * DIN;
    for (size_t i = (size_t)blockIdx.x * 256 + t; i < total; i += (size_t)512 * 256)
        s += fabsf(w1[i]);
    s = warp_sum(s);
    if ((t & 31) == 0) s_red[t >> 5] = s;
    __syncthreads();
    if (t < 32) {
        float v = (t < 8) ? s_red[t] : 0.f;
        v = warp_sum(v);
        if (t == 0) g_partial[blockIdx.x] = v;
    }
}

__global__ void k_w1_scale() {
    __shared__ float s_red[16];
    int t = threadIdx.x;  // 512
    float s = g_partial[t];
    s = warp_sum(s);
    if ((t & 31) == 0) s_red[t >> 5] = s;
    __syncthreads();
    if (t < 32) {
        float v = (t < 16) ? s_red[t] : 0.f;
        v = warp_sum(v);
        if (t == 0) {
            float mean = v / (float)((size_t)DH * DIN);
            float wm = fmaxf(mean, 1e-5f);
            g_scalars[0] = 1.0f / wm;   // s1
            g_scalars[2] = wm;          // 1/s1
        }
    }
}

__global__ void k_w2_scale(const float* __restrict__ w2) {
    __shared__ float s_red[16];
    int t = threadIdx.x;  // 512
    float s = 0.f;
    for (int i = t; i < DOUT * DH; i += 512) s += fabsf(w2[i]);
    s = warp_sum(s);
    if ((t & 31) == 0) s_red[t >> 5] = s;
    __syncthreads();
    if (t < 32) {
        float v = (t < 16) ? s_red[t] : 0.f;
        v = warp_sum(v);
        if (t == 0) {
            float mean = v / (float)(DOUT * DH);
            float wm = fmaxf(mean, 1e-5f);
            g_scalars[1] = 1.0f / wm;   // s2
            g_scalars[3] = wm;          // 1/s2
        }
    }
}

// ------------------------- weight quantization -------------------------
__global__ void k_quant_w1(const float* __restrict__ w1) {
    int row = blockIdx.x;
    float s1 = g_scalars[0];
    for (int c = threadIdx.x; c < KPAD; c += 256) {
        float t = 0.f;
        if (c < DIN) {
            t = rintf(w1[(size_t)row * DIN + c] * s1);
            t = fmaxf(-1.f, fminf(1.f, t));
        }
        g_w1q[(size_t)row * KPAD + c] = (signed char)(int)t;
    }
}

__global__ void k_quant_w2(const float* __restrict__ w2) {
    int i = blockIdx.x * 256 + threadIdx.x;
    if (i < DOUT * DH) {
        float t = rintf(w2[i] * g_scalars[1]);
        t = fmaxf(-1.f, fminf(1.f, t));
        g_w2q[i] = (signed char)(int)t;
    }
}

// ------------------------- activation quantization (layer 1 input) -------------------------
__global__ void __launch_bounds__(256) k_quant_x(const float* __restrict__ x) {
    __shared__ float sred[8];
    int row = blockIdx.x, t = threadIdx.x;
    const float* xr = x + (size_t)row * DIN;
    float v0 = xr[t];
    float v1 = xr[t + 256];
    float v2 = xr[t + 512];
    float v3 = (t < 16) ? xr[t + 768] : 0.f;

    float ss = v0 * v0 + v1 * v1 + v2 * v2 + v3 * v3;
    ss = warp_sum(ss);
    if ((t & 31) == 0) sred[t >> 5] = ss;
    __syncthreads();
    float tot = sred[0] + sred[1] + sred[2] + sred[3] + sred[4] + sred[5] + sred[6] + sred[7];
    float r = 1.0f / sqrtf(tot / (float)DIN + 1e-6f);

    float n0 = v0 * r, n1 = v1 * r, n2 = v2 * r, n3 = v3 * r;
    float am = fmaxf(fmaxf(fabsf(n0), fabsf(n1)), fmaxf(fabsf(n2), fabsf(n3)));
    __syncthreads();
    am = warp_max(am);
    if ((t & 31) == 0) sred[t >> 5] = am;
    __syncthreads();
    float amax = fmaxf(fmaxf(fmaxf(sred[0], sred[1]), fmaxf(sred[2], sred[3])),
                       fmaxf(fmaxf(sred[4], sred[5]), fmaxf(sred[6], sred[7])));
    float scale = 127.f / fmaxf(amax, 1e-5f);

    signed char* xo = g_xq + (size_t)row * KPAD;
    float k0 = fminf(fmaxf(rintf(n0 * scale), -128.f), 127.f);
    float k1 = fminf(fmaxf(rintf(n1 * scale), -128.f), 127.f);
    float k2 = fminf(fmaxf(rintf(n2 * scale), -128.f), 127.f);
    float k3 = fminf(fmaxf(rintf(n3 * scale), -128.f), 127.f);
    xo[t]       = (signed char)(int)k0;
    xo[t + 256] = (signed char)(int)k1;
    xo[t + 512] = (signed char)(int)k2;
    if (t < 64) xo[t + 768] = (signed char)(int)((t < 16) ? k3 : 0.f);
    if (t == 0) g_ax[row] = 1.0f / scale;
}

// ------------------------- IMMA GEMM (layer 1) -------------------------
// CTA tile: 128 (M, x rows) x 128 (N, w1 rows), K-chunks of 64 int8.
// smem rows padded to 80 bytes for conflict-free LDS fragment loads.
constexpr int ROWB       = 80;            // padded smem row stride (bytes)
constexpr int TILE_BYTES = 128 * ROWB;    // 10240
constexpr int STAGE      = 2 * TILE_BYTES;
constexpr int NSTAGE     = 4;
constexpr int GEMM_SMEM  = NSTAGE * STAGE;  // 81920

DI void load_stage(uint32_t smem_base, const char* gA, const char* gB,
                   int chunk, int buf, int tid) {
    uint32_t sA = smem_base + buf * STAGE;
    uint32_t sB = sA + TILE_BYTES;
    int koff = chunk * 64;
#pragma unroll
    for (int i = 0; i < 2; i++) {
        int q = tid + i * 256;
        int r = q >> 2, c = (q & 3) * 16;
        cp16(sA + r * ROWB + c, gA + (size_t)r * KPAD + koff + c);
    }
#pragma unroll
    for (int i = 0; i < 2; i++) {
        int q = tid + i * 256;
        int r = q >> 2, c = (q & 3) * 16;
        cp16(sB + r * ROWB + c, gB + (size_t)r * KPAD + koff + c);
    }
    asm volatile("cp.async.commit_group;" ::: "memory");
}

__global__ void __launch_bounds__(256) k_gemm(const float* __restrict__ b1) {
    extern __shared__ char smem[];
    const uint32_t smem_base = smem_u32(smem);
    const int tid = threadIdx.x;
    const int wid = tid >> 5;
    const int lid = tid & 31;
    const int g   = lid >> 2;   // group id (0..7)
    const int tig = lid & 3;    // thread-in-group

    const int warp_m = wid & 1;       // 0..1  -> M offset 64*warp_m
    const int warp_n = wid >> 1;      // 0..3  -> N offset 32*warp_n

    const int colbase = blockIdx.x * 128;  // over DH (w1 rows)
    const int rowbase = blockIdx.y * 128;  // over BROWS (x rows)

    const char* gA = (const char*)(g_xq + (size_t)rowbase * KPAD);
    const char* gB = (const char*)(g_w1q + (size_t)colbase * KPAD);

    load_stage(smem_base, gA, gB, 0, 0, tid);
    load_stage(smem_base, gA, gB, 1, 1, tid);
    load_stage(smem_base, gA, gB, 2, 2, tid);

    int acc[4][4][4];
#pragma unroll
    for (int mf = 0; mf < 4; mf++)
#pragma unroll
        for (int nf = 0; nf < 4; nf++)
#pragma unroll
            for (int r = 0; r < 4; r++) acc[mf][nf][r] = 0;

    for (int i = 0; i < NCHUNK; i++) {
        if (i < NCHUNK - 2)      asm volatile("cp.async.wait_group 2;" ::: "memory");
        else if (i == NCHUNK - 2) asm volatile("cp.async.wait_group 1;" ::: "memory");
        else                      asm volatile("cp.async.wait_group 0;" ::: "memory");
        __syncthreads();

        if (i + 3 < NCHUNK)
            load_stage(smem_base, gA, gB, i + 3, (i + 3) & 3, tid);

        uint32_t sA = smem_base + (i & 3) * STAGE;
        uint32_t sB = sA + TILE_BYTES;

#pragma unroll
        for (int ks = 0; ks < 2; ks++) {
            uint32_t a[4][4];
#pragma unroll
            for (int mf = 0; mf < 4; mf++) {
                uint32_t base = sA + (uint32_t)(warp_m * 64 + mf * 16 + g) * ROWB
                              + ks * 32 + tig * 4;
                a[mf][0] = lds32(base);
                a[mf][1] = lds32(base + 8 * ROWB);
                a[mf][2] = lds32(base + 16);
                a[mf][3] = lds32(base + 8 * ROWB + 16);
            }
#pragma unroll
            for (int nf = 0; nf < 4; nf++) {
                uint32_t bbase = sB + (uint32_t)(warp_n * 32 + nf * 8 + g) * ROWB
                               + ks * 32 + tig * 4;
                uint32_t b0 = lds32(bbase);
                uint32_t b1v = lds32(bbase + 16);
#pragma unroll
                for (int mf = 0; mf < 4; mf++)
                    mma_s8(acc[mf][nf], a[mf][0], a[mf][1], a[mf][2], a[mf][3], b0, b1v);
            }
        }
    }

    // ------------- epilogue: h = relu(P * ax_row * wm1 + b1_col) -------------
    float wm1 = g_scalars[2];
    float axw0[4], axw1[4];
#pragma unroll
    for (int mf = 0; mf < 4; mf++) {
        int r0 = rowbase + warp_m * 64 + mf * 16 + g;
        axw0[mf] = __ldg(g_ax + r0) * wm1;
        axw1[mf] = __ldg(g_ax + r0 + 8) * wm1;
    }
    float2 bias[4];
#pragma unroll
    for (int nf = 0; nf < 4; nf++) {
        int col = colbase + warp_n * 32 + nf * 8 + tig * 2;
        bias[nf] = *(const float2*)(b1 + col);
    }

#pragma unroll
    for (int mf = 0; mf < 4; mf++) {
        int r0 = rowbase + warp_m * 64 + mf * 16 + g;
#pragma unroll
        for (int nf = 0; nf < 4; nf++) {
            int col = colbase + warp_n * 32 + nf * 8 + tig * 2;
            float2 v0, v1;
            v0.x = fmaxf(fmaf((float)acc[mf][nf][0], axw0[mf], bias[nf].x), 0.f);
            v0.y = fmaxf(fmaf((float)acc[mf][nf][1], axw0[mf], bias[nf].y), 0.f);
            v1.x = fmaxf(fmaf((float)acc[mf][nf][2], axw1[mf], bias[nf].x), 0.f);
            v1.y = fmaxf(fmaf((float)acc[mf][nf][3], axw1[mf], bias[nf].y), 0.f);
            *(float2*)(g_h + (size_t)r0 * DH + col) = v0;
            *(float2*)(g_h + (size_t)(r0 + 8) * DH + col) = v1;
        }
    }
}

// ------------------------- fused layer 2 -------------------------
__global__ void __launch_bounds__(256) k_layer2(const float* __restrict__ b2,
                                                float* __restrict__ out) {
    extern __shared__ int sw2[];  // 10240 ints = 40 KB (w2 ternary int8, packed 4/int)
    __shared__ float fr[8];
    __shared__ int ir[80];
    int t = threadIdx.x;
    int w = t >> 5, l = t & 31;

    {
        const int4* src = (const int4*)g_w2q;
        int4* dst = (int4*)sw2;
#pragma unroll
        for (int i = 0; i < 10; i++) dst[t + i * 256] = src[t + i * 256];
    }
    float wm2 = g_scalars[3];
    __syncthreads();

    int rowbase = blockIdx.x * 4;
    for (int rr = 0; rr < 4; rr++) {
        int row = rowbase + rr;
        const float4* h4 = (const float4*)(g_h + (size_t)row * DH);
        float4 hv[4];
#pragma unroll
        for (int u = 0; u < 4; u++) hv[u] = h4[u * 256 + t];

        float ss = 0.f;
#pragma unroll
        for (int u = 0; u < 4; u++)
            ss += hv[u].x * hv[u].x + hv[u].y * hv[u].y + hv[u].z * hv[u].z + hv[u].w * hv[u].w;
        ss = warp_sum(ss);
        if (l == 0) fr[w] = ss;
        __syncthreads();
        float tot = fr[0] + fr[1] + fr[2] + fr[3] + fr[4] + fr[5] + fr[6] + fr[7];
        float r = 1.0f / sqrtf(tot / (float)DH + 1e-6f);

        float am = 0.f;
#pragma unroll
        for (int u = 0; u < 4; u++) {
            am = fmaxf(am, fabsf(hv[u].x * r));
            am = fmaxf(am, fabsf(hv[u].y * r));
            am = fmaxf(am, fabsf(hv[u].z * r));
            am = fmaxf(am, fabsf(hv[u].w * r));
        }
        __syncthreads();
        am = warp_max(am);
        if (l == 0) fr[w] = am;
        __syncthreads();
        float amax = fmaxf(fmaxf(fmaxf(fr[0], fr[1]), fmaxf(fr[2], fr[3])),
                           fmaxf(fmaxf(fr[4], fr[5]), fmaxf(fr[6], fr[7])));
        float scale = 127.f / fmaxf(amax, 1e-5f);
        float sr = r * scale;

        int xp[4];
#pragma unroll
        for (int u = 0; u < 4; u++) {
            int k0 = (int)fminf(fmaxf(rintf(hv[u].x * sr), -128.f), 127.f);
            int k1 = (int)fminf(fmaxf(rintf(hv[u].y * sr), -128.f), 127.f);
            int k2 = (int)fminf(fmaxf(rintf(hv[u].z * sr), -128.f), 127.f);
            int k3 = (int)fminf(fmaxf(rintf(hv[u].w * sr), -128.f), 127.f);
            xp[u] = (k0 & 0xFF) | ((k1 & 0xFF) << 8) | ((k2 & 0xFF) << 16) | (k3 << 24);
        }

        int acc[10];
#pragma unroll
        for (int j = 0; j < 10; j++) {
            int a = 0;
#pragma unroll
            for (int u = 0; u < 4; u++)
                a = __dp4a(xp[u], sw2[j * 1024 + u * 256 + t], a);
            acc[j] = a;
        }
#pragma unroll
        for (int j = 0; j < 10; j++) {
            int s = warp_isum(acc[j]);
            if (l == 0) ir[j * 8 + w] = s;
        }
        __syncthreads();
        if (t < 10) {
            int s = 0;
#pragma unroll
            for (int k = 0; k < 8; k++) s += ir[t * 8 + k];
            out[(size_t)row * DOUT + t] = (float)s * (1.0f / scale) * wm2 + b2[t];
        }
        __syncthreads();
    }
}

// ------------------------- launch -------------------------
extern "C" void kernel_launch(void* const* d_in, const int* in_sizes, int n_in,
                              void* d_out, int out_size) {
    const float* x  = (const float*)d_in[0];
    const float* w1 = (const float*)d_in[1];
    const float* b1 = (const float*)d_in[2];
    const float* w2 = (const float*)d_in[3];
    const float* b2 = (const float*)d_in[4];
    float* out = (float*)d_out;

    cudaFuncSetAttribute(k_gemm, cudaFuncAttributeMaxDynamicSharedMemorySize, GEMM_SMEM);

    k_w1_partial<<<512, 256>>>(w1);
    k_w1_scale<<<1, 512>>>();
    k_w2_scale<<<1, 512>>>(w2);
    k_quant_w1<<<DH, 256>>>(w1);
    k_quant_w2<<<(DOUT * DH + 255) / 256, 256>>>(w2);
    k_quant_x<<<BROWS, 256>>>(x);
    k_gemm<<<dim3(DH / 128, BROWS / 128), 256, GEMM_SMEM>>>(b1);
    k_layer2<<<BROWS / 4, 256, DOUT * DH * (int)sizeof(signed char)>>>(b2, out);
}

// round 4
// speedup vs baseline: 1.0210x; 1.0210x over previous
#include <cuda_runtime.h>
#include <cuda_bf16.h>
#include <stdint.h>
#include <stddef.h>

#define DI __device__ __forceinline__

constexpr int BROWS = 16384;
constexpr int DIN   = 784;
constexpr int DH    = 4096;
constexpr int DOUT  = 10;
constexpr int KPAD  = 832;           // 784 padded to 13 chunks of 64
constexpr int NCHUNK = 13;

// ------------------------- scratch (device globals) -------------------------
__device__ __align__(1024) signed char g_xq[(size_t)BROWS * KPAD];   // 13.6 MB
__device__ __align__(1024) signed char g_w1q[(size_t)DH * KPAD];     // 3.4 MB
__device__ __align__(1024) float       g_h[(size_t)BROWS * DH];      // 268 MB
__device__ __align__(16)   signed char g_w2q[DOUT * DH];             // 40 KB
__device__ float g_ax[BROWS];
// [0]=s1 (w1 quant scale) [1]=s2 [2]=1/s1 (=wm1) [3]=1/s2 (=wm2)
__device__ float g_scalars[4];
__device__ float g_partial[512];

// ------------------------- small helpers -------------------------
DI float warp_sum(float v) {
#pragma unroll
    for (int o = 16; o > 0; o >>= 1) v += __shfl_xor_sync(0xffffffffu, v, o);
    return v;
}
DI float warp_max(float v) {
#pragma unroll
    for (int o = 16; o > 0; o >>= 1) v = fmaxf(v, __shfl_xor_sync(0xffffffffu, v, o));
    return v;
}
DI int warp_isum(int v) {
#pragma unroll
    for (int o = 16; o > 0; o >>= 1) v += __shfl_xor_sync(0xffffffffu, v, o);
    return v;
}
DI uint32_t smem_u32(const void* p) {
    uint32_t a;
    asm("{ .reg .u64 t; cvta.to.shared.u64 t, %1; cvt.u32.u64 %0, t; }" : "=r"(a) : "l"(p));
    return a;
}
DI void cp16(uint32_t dst, const void* src) {
    asm volatile("cp.async.cg.shared.global [%0], [%1], 16;" :: "r"(dst), "l"(src));
}
DI void ldmA(uint32_t* a, uint32_t addr) {
    asm volatile("ldmatrix.sync.aligned.m8n8.x4.shared.b16 {%0,%1,%2,%3}, [%4];"
                 : "=r"(a[0]), "=r"(a[1]), "=r"(a[2]), "=r"(a[3]) : "r"(addr));
}
DI void ldmB(uint32_t* b, uint32_t addr) {
    asm volatile("ldmatrix.sync.aligned.m8n8.x2.shared.b16 {%0,%1}, [%2];"
                 : "=r"(b[0]), "=r"(b[1]) : "r"(addr));
}
DI void mma_s8(int* c, uint32_t a0, uint32_t a1, uint32_t a2, uint32_t a3,
               uint32_t b0, uint32_t b1) {
    asm volatile(
        "mma.sync.aligned.m16n8k32.row.col.s32.s8.s8.s32 "
        "{%0,%1,%2,%3}, {%4,%5,%6,%7}, {%8,%9}, {%0,%1,%2,%3};"
        : "+r"(c[0]), "+r"(c[1]), "+r"(c[2]), "+r"(c[3])
        : "r"(a0), "r"(a1), "r"(a2), "r"(a3), "r"(b0), "r"(b1));
}

// ------------------------- weight-scale reductions -------------------------
__global__ void k_w1_partial(const float* __restrict__ w1) {
    __shared__ float s_red[8];
    int t = threadIdx.x;
    float s = 0.f;
    const size_t total = (size_t)DH * DIN;
    for (size_t i = (size_t)blockIdx.x * 256 + t; i < total; i += (size_t)512 * 256)
        s += fabsf(w1[i]);
    s = warp_sum(s);
    if ((t & 31) == 0) s_red[t >> 5] = s;
    __syncthreads();
    if (t < 32) {
        float v = (t < 8) ? s_red[t] : 0.f;
        v = warp_sum(v);
        if (t == 0) g_partial[blockIdx.x] = v;
    }
}

__global__ void k_w1_scale() {
    __shared__ float s_red[16];
    int t = threadIdx.x;  // 512
    float s = g_partial[t];
    s = warp_sum(s);
    if ((t & 31) == 0) s_red[t >> 5] = s;
    __syncthreads();
    if (t < 32) {
        float v = (t < 16) ? s_red[t] : 0.f;
        v = warp_sum(v);
        if (t == 0) {
            float mean = v / (float)((size_t)DH * DIN);
            float wm = fmaxf(mean, 1e-5f);
            g_scalars[0] = 1.0f / wm;   // s1
            g_scalars[2] = wm;          // 1/s1
        }
    }
}

__global__ void k_w2_scale(const float* __restrict__ w2) {
    __shared__ float s_red[16];
    int t = threadIdx.x;  // 512
    float s = 0.f;
    for (int i = t; i < DOUT * DH; i += 512) s += fabsf(w2[i]);
    s = warp_sum(s);
    if ((t & 31) == 0) s_red[t >> 5] = s;
    __syncthreads();
    if (t < 32) {
        float v = (t < 16) ? s_red[t] : 0.f;
        v = warp_sum(v);
        if (t == 0) {
            float mean = v / (float)(DOUT * DH);
            float wm = fmaxf(mean, 1e-5f);
            g_scalars[1] = 1.0f / wm;   // s2
            g_scalars[3] = wm;          // 1/s2
        }
    }
}

// ------------------------- weight quantization -------------------------
__global__ void k_quant_w1(const float* __restrict__ w1) {
    int row = blockIdx.x;
    float s1 = g_scalars[0];
    for (int c = threadIdx.x; c < KPAD; c += 256) {
        float t = 0.f;
        if (c < DIN) {
            t = rintf(w1[(size_t)row * DIN + c] * s1);
            t = fmaxf(-1.f, fminf(1.f, t));
        }
        g_w1q[(size_t)row * KPAD + c] = (signed char)(int)t;
    }
}

__global__ void k_quant_w2(const float* __restrict__ w2) {
    int i = blockIdx.x * 256 + threadIdx.x;
    if (i < DOUT * DH) {
        float t = rintf(w2[i] * g_scalars[1]);
        t = fmaxf(-1.f, fminf(1.f, t));
        g_w2q[i] = (signed char)(int)t;
    }
}

// ------------------------- activation quantization (layer 1 input) -------------------------
__global__ void __launch_bounds__(256) k_quant_x(const float* __restrict__ x) {
    __shared__ float sred[8];
    int row = blockIdx.x, t = threadIdx.x;
    const float* xr = x + (size_t)row * DIN;
    float v0 = xr[t];
    float v1 = xr[t + 256];
    float v2 = xr[t + 512];
    float v3 = (t < 16) ? xr[t + 768] : 0.f;

    float ss = v0 * v0 + v1 * v1 + v2 * v2 + v3 * v3;
    ss = warp_sum(ss);
    if ((t & 31) == 0) sred[t >> 5] = ss;
    __syncthreads();
    float tot = sred[0] + sred[1] + sred[2] + sred[3] + sred[4] + sred[5] + sred[6] + sred[7];
    float r = 1.0f / sqrtf(tot / (float)DIN + 1e-6f);

    float n0 = v0 * r, n1 = v1 * r, n2 = v2 * r, n3 = v3 * r;
    float am = fmaxf(fmaxf(fabsf(n0), fabsf(n1)), fmaxf(fabsf(n2), fabsf(n3)));
    __syncthreads();
    am = warp_max(am);
    if ((t & 31) == 0) sred[t >> 5] = am;
    __syncthreads();
    float amax = fmaxf(fmaxf(fmaxf(sred[0], sred[1]), fmaxf(sred[2], sred[3])),
                       fmaxf(fmaxf(sred[4], sred[5]), fmaxf(sred[6], sred[7])));
    float scale = 127.f / fmaxf(amax, 1e-5f);

    signed char* xo = g_xq + (size_t)row * KPAD;
    float k0 = fminf(fmaxf(rintf(n0 * scale), -128.f), 127.f);
    float k1 = fminf(fmaxf(rintf(n1 * scale), -128.f), 127.f);
    float k2 = fminf(fmaxf(rintf(n2 * scale), -128.f), 127.f);
    float k3 = fminf(fmaxf(rintf(n3 * scale), -128.f), 127.f);
    xo[t]       = (signed char)(int)k0;
    xo[t + 256] = (signed char)(int)k1;
    xo[t + 512] = (signed char)(int)k2;
    if (t < 64) xo[t + 768] = (signed char)(int)((t < 16) ? k3 : 0.f);
    if (t == 0) g_ax[row] = 1.0f / scale;
}

// ------------------------- IMMA GEMM (layer 1) -------------------------
// CTA tile: 128 (M) x 128 (N), K-chunks of 64 int8.
// smem: 64B rows, XOR swizzle slot = cg ^ ((row>>1)&3); conflict-free for
// cp.async 16B stores and ldmatrix 8-row phases.
constexpr int TILE_BYTES = 128 * 64;      // 8192
constexpr int STAGE      = 2 * TILE_BYTES;
constexpr int NSTAGE     = 4;
constexpr int GEMM_SMEM  = NSTAGE * STAGE;  // 65536

DI void load_stage(uint32_t smem_base, const char* gA, const char* gB,
                   int chunk, int buf, int tid) {
    uint32_t sA = smem_base + buf * STAGE;
    uint32_t sB = sA + TILE_BYTES;
    int koff = chunk * 64;
#pragma unroll
    for (int i = 0; i < 2; i++) {
        int q = tid + i * 256;
        int r = q >> 2, c = q & 3;
        uint32_t off = (uint32_t)r * 64 + (uint32_t)((c ^ ((r >> 1) & 3)) << 4);
        cp16(sA + off, gA + (size_t)r * KPAD + koff + c * 16);
        cp16(sB + off, gB + (size_t)r * KPAD + koff + c * 16);
    }
    asm volatile("cp.async.commit_group;" ::: "memory");
}

__global__ void __launch_bounds__(256) k_gemm(const float* __restrict__ b1) {
    extern __shared__ char smem[];
    const uint32_t smem_base = smem_u32(smem);
    const int tid = threadIdx.x;
    const int wid = tid >> 5;
    const int lid = tid & 31;
    const int g   = lid >> 2;   // group id (0..7)
    const int tig = lid & 3;    // thread-in-group

    const int warp_m = wid & 1;       // 0..1  -> M offset 64*warp_m
    const int warp_n = wid >> 1;      // 0..3  -> N offset 32*warp_n

    const int colbase = blockIdx.x * 128;  // over DH (w1 rows)
    const int rowbase = blockIdx.y * 128;  // over BROWS (x rows)

    const char* gA = (const char*)(g_xq + (size_t)rowbase * KPAD);
    const char* gB = (const char*)(g_w1q + (size_t)colbase * KPAD);

    load_stage(smem_base, gA, gB, 0, 0, tid);
    load_stage(smem_base, gA, gB, 1, 1, tid);
    load_stage(smem_base, gA, gB, 2, 2, tid);

    // ldmatrix per-lane addressing
    // A (x4): lanes 0-7 rows+0..7 cg(2ks); 8-15 rows+8 cg(2ks); 16-23 rows+0 cg(2ks+1); 24-31 rows+8 cg(2ks+1)
    const int rowA = warp_m * 64 + ((lid >> 3) & 1) * 8 + (lid & 7);
    const int cgA  = lid >> 4;                 // 0/1 -> k-half select
    const uint32_t swA = (uint32_t)((rowA >> 1) & 3);
    // B (x2): lanes 0-7 rows+0..7 cg(2ks); 8-15 rows cg(2ks+1). (lanes 16-31 mirror, ignored)
    const int rowB = warp_n * 32 + (lid & 7);
    const int cgB  = (lid >> 3) & 1;
    const uint32_t swB = (uint32_t)((rowB >> 1) & 3);

    int acc[4][4][4];
#pragma unroll
    for (int mf = 0; mf < 4; mf++)
#pragma unroll
        for (int nf = 0; nf < 4; nf++)
#pragma unroll
            for (int r = 0; r < 4; r++) acc[mf][nf][r] = 0;

    for (int i = 0; i < NCHUNK; i++) {
        if (i < NCHUNK - 2)       asm volatile("cp.async.wait_group 2;" ::: "memory");
        else if (i == NCHUNK - 2) asm volatile("cp.async.wait_group 1;" ::: "memory");
        else                      asm volatile("cp.async.wait_group 0;" ::: "memory");
        __syncthreads();

        if (i + 3 < NCHUNK)
            load_stage(smem_base, gA, gB, i + 3, (i + 3) & 3, tid);

        uint32_t sA = smem_base + (i & 3) * STAGE;
        uint32_t sB = sA + TILE_BYTES;

#pragma unroll
        for (int ks = 0; ks < 2; ks++) {
            uint32_t aoff = (uint32_t)(((2 * ks + cgA) ^ swA) << 4);
            uint32_t boff = (uint32_t)(((2 * ks + cgB) ^ swB) << 4);
            uint32_t a[4][4];
#pragma unroll
            for (int mf = 0; mf < 4; mf++)
                ldmA(a[mf], sA + (uint32_t)(rowA + mf * 16) * 64 + aoff);
#pragma unroll
            for (int nf = 0; nf < 4; nf++) {
                uint32_t b[2];
                ldmB(b, sB + (uint32_t)(rowB + nf * 8) * 64 + boff);
#pragma unroll
                for (int mf = 0; mf < 4; mf++)
                    mma_s8(acc[mf][nf], a[mf][0], a[mf][1], a[mf][2], a[mf][3], b[0], b[1]);
            }
        }
    }

    // ------------- epilogue: h = relu(P * ax_row * wm1 + b1_col) -------------
    float wm1 = g_scalars[2];
    float axw0[4], axw1[4];
#pragma unroll
    for (int mf = 0; mf < 4; mf++) {
        int r0 = rowbase + warp_m * 64 + mf * 16 + g;
        axw0[mf] = __ldg(g_ax + r0) * wm1;
        axw1[mf] = __ldg(g_ax + r0 + 8) * wm1;
    }
    float2 bias[4];
#pragma unroll
    for (int nf = 0; nf < 4; nf++) {
        int col = colbase + warp_n * 32 + nf * 8 + tig * 2;
        bias[nf] = *(const float2*)(b1 + col);
    }

#pragma unroll
    for (int mf = 0; mf < 4; mf++) {
        int r0 = rowbase + warp_m * 64 + mf * 16 + g;
#pragma unroll
        for (int nf = 0; nf < 4; nf++) {
            int col = colbase + warp_n * 32 + nf * 8 + tig * 2;
            float2 v0, v1;
            v0.x = fmaxf(fmaf((float)acc[mf][nf][0], axw0[mf], bias[nf].x), 0.f);
            v0.y = fmaxf(fmaf((float)acc[mf][nf][1], axw0[mf], bias[nf].y), 0.f);
            v1.x = fmaxf(fmaf((float)acc[mf][nf][2], axw1[mf], bias[nf].x), 0.f);
            v1.y = fmaxf(fmaf((float)acc[mf][nf][3], axw1[mf], bias[nf].y), 0.f);
            *(float2*)(g_h + (size_t)r0 * DH + col) = v0;
            *(float2*)(g_h + (size_t)(r0 + 8) * DH + col) = v1;
        }
    }
}

// ------------------------- fused layer 2 -------------------------
__global__ void __launch_bounds__(256) k_layer2(const float* __restrict__ b2,
                                                float* __restrict__ out) {
    extern __shared__ int sw2[];  // 10240 ints = 40 KB (w2 ternary int8, packed 4/int)
    __shared__ float fr[8];
    __shared__ int ir[80];
    int t = threadIdx.x;
    int w = t >> 5, l = t & 31;

    {
        const int4* src = (const int4*)g_w2q;
        int4* dst = (int4*)sw2;
#pragma unroll
        for (int i = 0; i < 10; i++) dst[t + i * 256] = src[t + i * 256];
    }
    float wm2 = g_scalars[3];
    __syncthreads();

    int rowbase = blockIdx.x * 4;
    for (int rr = 0; rr < 4; rr++) {
        int row = rowbase + rr;
        const float4* h4 = (const float4*)(g_h + (size_t)row * DH);
        float4 hv[4];
#pragma unroll
        for (int u = 0; u < 4; u++) hv[u] = h4[u * 256 + t];

        float ss = 0.f;
#pragma unroll
        for (int u = 0; u < 4; u++)
            ss += hv[u].x * hv[u].x + hv[u].y * hv[u].y + hv[u].z * hv[u].z + hv[u].w * hv[u].w;
        ss = warp_sum(ss);
        if (l == 0) fr[w] = ss;
        __syncthreads();
        float tot = fr[0] + fr[1] + fr[2] + fr[3] + fr[4] + fr[5] + fr[6] + fr[7];
        float r = 1.0f / sqrtf(tot / (float)DH + 1e-6f);

        float am = 0.f;
#pragma unroll
        for (int u = 0; u < 4; u++) {
            am = fmaxf(am, fabsf(hv[u].x * r));
            am = fmaxf(am, fabsf(hv[u].y * r));
            am = fmaxf(am, fabsf(hv[u].z * r));
            am = fmaxf(am, fabsf(hv[u].w * r));
        }
        __syncthreads();
        am = warp_max(am);
        if (l == 0) fr[w] = am;
        __syncthreads();
        float amax = fmaxf(fmaxf(fmaxf(fr[0], fr[1]), fmaxf(fr[2], fr[3])),
                           fmaxf(fmaxf(fr[4], fr[5]), fmaxf(fr[6], fr[7])));
        float scale = 127.f / fmaxf(amax, 1e-5f);
        float sr = r * scale;

        int xp[4];
#pragma unroll
        for (int u = 0; u < 4; u++) {
            int k0 = (int)fminf(fmaxf(rintf(hv[u].x * sr), -128.f), 127.f);
            int k1 = (int)fminf(fmaxf(rintf(hv[u].y * sr), -128.f), 127.f);
            int k2 = (int)fminf(fmaxf(rintf(hv[u].z * sr), -128.f), 127.f);
            int k3 = (int)fminf(fmaxf(rintf(hv[u].w * sr), -128.f), 127.f);
            xp[u] = (k0 & 0xFF) | ((k1 & 0xFF) << 8) | ((k2 & 0xFF) << 16) | (k3 << 24);
        }

        int acc[10];
#pragma unroll
        for (int j = 0; j < 10; j++) {
            int a = 0;
#pragma unroll
            for (int u = 0; u < 4; u++)
                a = __dp4a(xp[u], sw2[j * 1024 + u * 256 + t], a);
            acc[j] = a;
        }
#pragma unroll
        for (int j = 0; j < 10; j++) {
            int s = warp_isum(acc[j]);
            if (l == 0) ir[j * 8 + w] = s;
        }
        __syncthreads();
        if (t < 10) {
            int s = 0;
#pragma unroll
            for (int k = 0; k < 8; k++) s += ir[t * 8 + k];
            out[(size_t)row * DOUT + t] = (float)s * (1.0f / scale) * wm2 + b2[t];
        }
        __syncthreads();
    }
}

// ------------------------- launch -------------------------
extern "C" void kernel_launch(void* const* d_in, const int* in_sizes, int n_in,
                              void* d_out, int out_size) {
    const float* x  = (const float*)d_in[0];
    const float* w1 = (const float*)d_in[1];
    const float* b1 = (const float*)d_in[2];
    const float* w2 = (const float*)d_in[3];
    const float* b2 = (const float*)d_in[4];
    float* out = (float*)d_out;

    cudaFuncSetAttribute(k_gemm, cudaFuncAttributeMaxDynamicSharedMemorySize, GEMM_SMEM);

    // Order chosen so k_gemm is the 6th launch (ncu capture: -s 5 -c 1)
    k_w1_partial<<<512, 256>>>(w1);     // 1
    k_w1_scale<<<1, 512>>>();           // 2
    k_quant_x<<<BROWS, 256>>>(x);       // 3
    k_quant_w1<<<DH, 256>>>(w1);        // 4
    k_w2_scale<<<1, 512>>>(w2);         // 5
    k_gemm<<<dim3(DH / 128, BROWS / 128), 256, GEMM_SMEM>>>(b1);  // 6
    k_quant_w2<<<(DOUT * DH + 255) / 256, 256>>>(w2);             // 7
    k_layer2<<<BROWS / 4, 256, DOUT * DH * (int)sizeof(signed char)>>>(b2, out);  // 8
}